// round 1
// baseline (speedup 1.0000x reference)
#include <cuda_runtime.h>
#include <math.h>

// Problem constants
#define LL    4096
#define DD    64
#define MODES 64
#define BH    64          // B*H = 8*8
#define MM    128         // 2*MODES (re block then im block)
#define NSPLIT 4
#define KC    (LL / NSPLIT)   // 1024
#define TS    16              // k-chunk per smem stage
#define SCALE 0.125f          // D^-0.5

// ---------------- scratch (static device globals; no allocation) ----------------
__device__ float g_W[3][LL][MM];              // forward DFT basis per tensor: [n][mm], mm<64: cos, mm>=64: -sin
__device__ float g_WinvT[MM][LL];             // inverse basis transposed:   [k2][n]
__device__ float g_F[3][NSPLIT][BH][MM][DD];  // split-K partial spectra
__device__ float g_V2[BH][MM][DD];            // post-attention values (re block, im block)

// ---------------- basis construction (exact angles mod 2pi via integer arith) ----------------
__global__ __launch_bounds__(256) void build_basis_kernel(const int* __restrict__ iq,
                                                          const int* __restrict__ ik,
                                                          const int* __restrict__ iv) {
    const int FWD = 3 * LL * MODES;
    const int TOT = FWD + MODES * LL;
    for (int gid = blockIdx.x * blockDim.x + threadIdx.x; gid < TOT;
         gid += gridDim.x * blockDim.x) {
        if (gid < FWD) {
            int t  = gid / (LL * MODES);
            int r0 = gid - t * (LL * MODES);
            int n  = r0 >> 6;        // / MODES
            int m  = r0 & 63;
            const int* idx = (t == 0) ? iq : ((t == 1) ? ik : iv);
            int f = idx[m];
            int r = (f * n) & (LL - 1);          // exact phase: theta/pi = r/2048
            float s, c;
            sincospif((float)r * (1.0f / 2048.0f), &s, &c);
            g_W[t][n][m]         = c;            // Re basis
            g_W[t][n][MODES + m] = -s;           // Im basis (e^{-i theta})
        } else {
            int r0 = gid - FWD;
            int k  = r0 >> 12;       // / LL  (0..63)
            int n  = r0 & (LL - 1);
            if (k == 0) {
                g_WinvT[0][n]     = 1.0f / (float)LL;  // bin 0: Re only
                g_WinvT[MODES][n] = 0.0f;              // imag of bin 0 dropped by irfft
            } else {
                int r = (k * n) & (LL - 1);
                float s, c;
                sincospif((float)r * (1.0f / 2048.0f), &s, &c);
                g_WinvT[k][n]         =  2.0f * c / (float)LL;
                g_WinvT[MODES + k][n] = -2.0f * s / (float)LL;
            }
        }
    }
}

// ---------------- shared GEMM body: C[128 rows x 64 cols] = sum_k A[k][row] * B[k][col] ----------------
// A: element (k,col128) at A[k*lda + col], col in [0,128)
// B: element (k,d)      at B[k*64 + d]
// C: element (row,d)    at C[row*64 + d]
__device__ __forceinline__ void gemm_mm128_d64(const float* __restrict__ A, int lda,
                                               const float* __restrict__ Bp,
                                               float* __restrict__ C, int nch) {
    __shared__ float As[2][TS][MM];   // 16 KB
    __shared__ float Bs[2][TS][DD];   // 8 KB
    const int tid = threadIdx.x;
    const int ty  = tid >> 4;    // 0..15 -> output rows ty*8..ty*8+7
    const int tx  = tid & 15;    // 0..15 -> output cols tx*4..tx*4+3

    float acc[8][4];
#pragma unroll
    for (int i = 0; i < 8; i++)
#pragma unroll
        for (int j = 0; j < 4; j++) acc[i][j] = 0.0f;

    const int r0 = tid >> 5;               // A f4 slot 1: rows 0..7
    const int c0 = (tid & 31) << 2;
    const int r1 = (tid + 256) >> 5;       // A f4 slot 2: rows 8..15
    const int c1 = c0;
    const int rb = tid >> 4;               // B f4 slot
    const int cb = (tid & 15) << 2;

    // load chunk 0
    *(float4*)&As[0][r0][c0] = *(const float4*)&A[r0 * lda + c0];
    *(float4*)&As[0][r1][c1] = *(const float4*)&A[r1 * lda + c1];
    *(float4*)&Bs[0][rb][cb] = *(const float4*)&Bp[rb * DD + cb];
    __syncthreads();

    for (int ch = 0; ch < nch; ch++) {
        const int cur = ch & 1;
        float4 ra0, ra1, rb4;
        const bool pf = (ch + 1 < nch);
        if (pf) {
            const int kb = (ch + 1) * TS;
            ra0 = *(const float4*)&A[(kb + r0) * lda + c0];
            ra1 = *(const float4*)&A[(kb + r1) * lda + c1];
            rb4 = *(const float4*)&Bp[(kb + rb) * DD + cb];
        }
#pragma unroll
        for (int kk = 0; kk < TS; kk++) {
            float a[8], b[4];
            *(float4*)&a[0] = *(const float4*)&As[cur][kk][ty * 8];
            *(float4*)&a[4] = *(const float4*)&As[cur][kk][ty * 8 + 4];
            *(float4*)&b[0] = *(const float4*)&Bs[cur][kk][tx * 4];
#pragma unroll
            for (int i = 0; i < 8; i++)
#pragma unroll
                for (int j = 0; j < 4; j++) acc[i][j] = fmaf(a[i], b[j], acc[i][j]);
        }
        if (pf) {
            const int nxt = cur ^ 1;
            *(float4*)&As[nxt][r0][c0] = ra0;
            *(float4*)&As[nxt][r1][c1] = ra1;
            *(float4*)&Bs[nxt][rb][cb] = rb4;
            __syncthreads();
        }
    }
#pragma unroll
    for (int i = 0; i < 8; i++) {
        float4 o = make_float4(acc[i][0], acc[i][1], acc[i][2], acc[i][3]);
        *(float4*)&C[(ty * 8 + i) * DD + tx * 4] = o;
    }
}

// ---------------- stage 1: forward DFT (batched GEMM, split-K) ----------------
__global__ __launch_bounds__(256) void dft_fwd_kernel(const float* __restrict__ q,
                                                      const float* __restrict__ k,
                                                      const float* __restrict__ v) {
    const int split = blockIdx.x;   // 0..NSPLIT-1
    const int bh    = blockIdx.y;   // 0..63
    const int t     = blockIdx.z;   // 0..2
    const float* x  = (t == 0) ? q : ((t == 1) ? k : v);
    const float* A  = &g_W[t][split * KC][0];
    const float* Bp = x + (size_t)bh * LL * DD + (size_t)split * KC * DD;
    float* C        = &g_F[t][split][bh][0][0];
    gemm_mm128_d64(A, MM, Bp, C, KC / TS);
}

// ---------------- stage 2: complex attention over modes + complex tanh ----------------
#define SP 65   // padded smem row stride
__global__ __launch_bounds__(256) void attn_kernel() {
    extern __shared__ float sm[];
    float* Qs = sm;                 // [128][65]
    float* Ks = Qs + MM * SP;
    float* Vs = Ks + MM * SP;
    float* SR = Vs + MM * SP;       // [64][65]
    float* SI = SR + MODES * SP;

    const int bh  = blockIdx.x;
    const int tid = threadIdx.x;

    // reduce split-K partials into smem
    for (int e = tid; e < MM * DD; e += 256) {
        const int r = e >> 6, d = e & 63;
        float aq = 0.f, ak = 0.f, av = 0.f;
#pragma unroll
        for (int s = 0; s < NSPLIT; s++) {
            aq += g_F[0][s][bh][r][d];
            ak += g_F[1][s][bh][r][d];
            av += g_F[2][s][bh][r][d];
        }
        Qs[r * SP + d] = aq;
        Ks[r * SP + d] = ak;
        Vs[r * SP + d] = av;
    }
    __syncthreads();

    const int tm = tid >> 4;   // 0..15
    const int tn = tid & 15;   // 0..15

    // qk_ft = q_ft @ k_ft^T (no conj), then scale + complex tanh
    {
        float re[4][4], im[4][4];
#pragma unroll
        for (int i = 0; i < 4; i++)
#pragma unroll
            for (int j = 0; j < 4; j++) { re[i][j] = 0.f; im[i][j] = 0.f; }

        for (int d = 0; d < DD; d++) {
            float qr[4], qi[4], kr[4], ki[4];
#pragma unroll
            for (int i = 0; i < 4; i++) {
                qr[i] = Qs[(tm * 4 + i) * SP + d];
                qi[i] = Qs[(MODES + tm * 4 + i) * SP + d];
            }
#pragma unroll
            for (int j = 0; j < 4; j++) {
                kr[j] = Ks[(tn * 4 + j) * SP + d];
                ki[j] = Ks[(MODES + tn * 4 + j) * SP + d];
            }
#pragma unroll
            for (int i = 0; i < 4; i++)
#pragma unroll
                for (int j = 0; j < 4; j++) {
                    re[i][j] = fmaf(qr[i], kr[j], re[i][j]);
                    re[i][j] = fmaf(-qi[i], ki[j], re[i][j]);
                    im[i][j] = fmaf(qr[i], ki[j], im[i][j]);
                    im[i][j] = fmaf(qi[i], kr[j], im[i][j]);
                }
        }
#pragma unroll
        for (int i = 0; i < 4; i++)
#pragma unroll
            for (int j = 0; j < 4; j++) {
                const float x  = re[i][j] * SCALE;
                const float y  = im[i][j] * SCALE;
                const float x2 = 2.0f * x;
                float tr, ti;
                if (fabsf(x2) > 80.0f) {
                    tr = (x > 0.0f) ? 1.0f : -1.0f;
                    ti = 0.0f;
                } else {
                    const float y2 = 2.0f * y;
                    const float dn = coshf(x2) + cosf(y2);
                    tr = sinhf(x2) / dn;
                    ti = sinf(y2) / dn;
                }
                SR[(tm * 4 + i) * SP + tn * 4 + j] = tr;
                SI[(tm * 4 + i) * SP + tn * 4 + j] = ti;
            }
    }
    __syncthreads();

    // values = scores @ v_ft
    {
        float vr[4][4], vi[4][4];
#pragma unroll
        for (int i = 0; i < 4; i++)
#pragma unroll
            for (int j = 0; j < 4; j++) { vr[i][j] = 0.f; vi[i][j] = 0.f; }

        for (int n = 0; n < MODES; n++) {
            float sr[4], si[4], br[4], bi[4];
#pragma unroll
            for (int i = 0; i < 4; i++) {
                sr[i] = SR[(tm * 4 + i) * SP + n];
                si[i] = SI[(tm * 4 + i) * SP + n];
            }
#pragma unroll
            for (int j = 0; j < 4; j++) {
                br[j] = Vs[n * SP + tn * 4 + j];
                bi[j] = Vs[(MODES + n) * SP + tn * 4 + j];
            }
#pragma unroll
            for (int i = 0; i < 4; i++)
#pragma unroll
                for (int j = 0; j < 4; j++) {
                    vr[i][j] = fmaf(sr[i], br[j], vr[i][j]);
                    vr[i][j] = fmaf(-si[i], bi[j], vr[i][j]);
                    vi[i][j] = fmaf(sr[i], bi[j], vi[i][j]);
                    vi[i][j] = fmaf(si[i], br[j], vi[i][j]);
                }
        }
#pragma unroll
        for (int i = 0; i < 4; i++)
#pragma unroll
            for (int j = 0; j < 4; j++) {
                g_V2[bh][tm * 4 + i][tn * 4 + j]         = vr[i][j];
                g_V2[bh][MODES + tm * 4 + i][tn * 4 + j] = vi[i][j];
            }
    }
}

// ---------------- stage 3: inverse transform (GEMM) ----------------
__global__ __launch_bounds__(256) void dft_inv_kernel(float* __restrict__ out) {
    const int ntile = blockIdx.x;   // 0..31 (128 rows each)
    const int bh    = blockIdx.y;   // 0..63
    const float* A  = &g_WinvT[0][ntile * 128];
    const float* Bp = &g_V2[bh][0][0];
    float* C        = out + (size_t)bh * LL * DD + (size_t)ntile * 128 * DD;
    gemm_mm128_d64(A, LL, Bp, C, MM / TS);
}

// ---------------- entry point ----------------
extern "C" void kernel_launch(void* const* d_in, const int* in_sizes, int n_in,
                              void* d_out, int out_size) {
    const float* q  = (const float*)d_in[0];
    const float* k  = (const float*)d_in[1];
    const float* v  = (const float*)d_in[2];
    const int* iq   = (const int*)d_in[3];
    const int* ik   = (const int*)d_in[4];
    const int* iv   = (const int*)d_in[5];
    float* out      = (float*)d_out;

    build_basis_kernel<<<512, 256>>>(iq, ik, iv);
    dft_fwd_kernel<<<dim3(NSPLIT, BH, 3), 256>>>(q, k, v);

    const int attn_smem = (3 * MM + 2 * MODES) * SP * (int)sizeof(float);  // 133120 B
    cudaFuncSetAttribute(attn_kernel, cudaFuncAttributeMaxDynamicSharedMemorySize, attn_smem);
    attn_kernel<<<BH, 256, attn_smem>>>();

    dft_inv_kernel<<<dim3(LL / 128, BH), 256>>>(out);
}

// round 4
// speedup vs baseline: 1.1035x; 1.1035x over previous
#include <cuda_runtime.h>
#include <cuda_bf16.h>
#include <math.h>
#include <cstdint>

#define LL    4096
#define DD    64
#define MODES 64
#define BH    64
#define MM    128
#define NSPLIT 8
#define SCALE 0.125f

// ---------------- globals (no allocation) ----------------
__device__ float2   g_tab[LL];                     // cos/sin(2*pi*r/4096)
__device__ uint32_t g_WfPHi[3][8][256][32][4];     // fwd basis, A-fragment packed (hi)
__device__ uint32_t g_WfPMd[3][8][256][32][4];     // (mid)
__device__ uint32_t g_WfPLo[3][8][256][32][4];     // (lo)
__device__ uint32_t g_WiPHi[256][8][32][4];        // inv basis, A-fragment packed
__device__ uint32_t g_WiPLo[256][8][32][4];
__device__ float    g_F[3][NSPLIT][BH][MM][DD];    // split-K partial spectra
__device__ float    g_V2[BH][MM][DD];              // post-attention values

// ---------------- helpers ----------------
__device__ __forceinline__ uint32_t pack2(__nv_bfloat16 a, __nv_bfloat16 b) {
    return (uint32_t)__bfloat16_as_ushort(a) | ((uint32_t)__bfloat16_as_ushort(b) << 16);
}
__device__ __forceinline__ void split2(float a, float b, uint32_t& h, uint32_t& l) {
    __nv_bfloat16 ha = __float2bfloat16(a), hb = __float2bfloat16(b);
    __nv_bfloat16 la = __float2bfloat16(a - __bfloat162float(ha));
    __nv_bfloat16 lb = __float2bfloat16(b - __bfloat162float(hb));
    h = pack2(ha, hb);
    l = pack2(la, lb);
}
__device__ __forceinline__ void split3(float a, float b,
                                       uint32_t& h, uint32_t& m, uint32_t& l) {
    __nv_bfloat16 ha = __float2bfloat16(a), hb = __float2bfloat16(b);
    float ra = a - __bfloat162float(ha), rb = b - __bfloat162float(hb);
    __nv_bfloat16 ma = __float2bfloat16(ra), mb = __float2bfloat16(rb);
    __nv_bfloat16 la = __float2bfloat16(ra - __bfloat162float(ma));
    __nv_bfloat16 lb = __float2bfloat16(rb - __bfloat162float(mb));
    h = pack2(ha, hb);
    m = pack2(ma, mb);
    l = pack2(la, lb);
}

__device__ __forceinline__ void mma16816(float* c, const uint4& a, const uint2& b) {
    asm volatile(
        "mma.sync.aligned.m16n8k16.row.col.f32.bf16.bf16.f32 "
        "{%0,%1,%2,%3}, {%4,%5,%6,%7}, {%8,%9}, {%0,%1,%2,%3};"
        : "+f"(c[0]), "+f"(c[1]), "+f"(c[2]), "+f"(c[3])
        : "r"(a.x), "r"(a.y), "r"(a.z), "r"(a.w), "r"(b.x), "r"(b.y));
}

// ---------------- kernel 0: phase table ----------------
__global__ __launch_bounds__(256) void tab_kernel() {
    int r = blockIdx.x * blockDim.x + threadIdx.x;
    if (r < LL) {
        float s, c;
        sincospif((float)r * (1.0f / 2048.0f), &s, &c);
        g_tab[r] = make_float2(c, s);
    }
}

// ---------------- kernel 1: build fragment-packed bases ----------------
#define FWDN (3 * 8 * 256 * 32 * 4)   // 786432
#define INVN (256 * 8 * 32 * 4)       // 262144

__device__ __forceinline__ float invv(int n, int k2) {
    if (k2 == 0) return 1.0f / (float)LL;
    if (k2 == MODES) return 0.0f;
    if (k2 < MODES) {
        int r = (k2 * n) & (LL - 1);
        return 2.0f * g_tab[r].x * (1.0f / (float)LL);
    }
    int r = ((k2 - MODES) * n) & (LL - 1);
    return -2.0f * g_tab[r].y * (1.0f / (float)LL);
}

__global__ __launch_bounds__(256) void build_packed(const int* __restrict__ iq,
                                                    const int* __restrict__ ik,
                                                    const int* __restrict__ iv) {
    for (int gid = blockIdx.x * blockDim.x + threadIdx.x; gid < FWDN + INVN;
         gid += gridDim.x * blockDim.x) {
        if (gid < FWDN) {
            int r    = gid & 3;
            int lane = (gid >> 2) & 31;
            int ks   = (gid >> 7) & 255;
            int s    = (gid >> 15) & 7;
            int t    = gid >> 18;
            int m = s * 16 + (r & 1) * 8 + (lane >> 2);
            int k = ks * 16 + ((r >> 1) & 1) * 8 + (lane & 3) * 2;
            const int* ix = (t == 0) ? iq : ((t == 1) ? ik : iv);
            int f = ix[m & 63];
            int r1 = (f * k) & (LL - 1);
            int r2 = (r1 + f) & (LL - 1);
            float2 c1 = g_tab[r1], c2 = g_tab[r2];
            float v0 = (m < MODES) ? c1.x : -c1.y;
            float v1 = (m < MODES) ? c2.x : -c2.y;
            uint32_t h, mm_, l;
            split3(v0, v1, h, mm_, l);
            g_WfPHi[t][s][ks][lane][r] = h;
            g_WfPMd[t][s][ks][lane][r] = mm_;
            g_WfPLo[t][s][ks][lane][r] = l;
        } else {
            int g2    = gid - FWDN;
            int r     = g2 & 3;
            int lane  = (g2 >> 2) & 31;
            int ks    = (g2 >> 7) & 7;
            int strip = g2 >> 10;
            int n  = strip * 16 + (r & 1) * 8 + (lane >> 2);
            int k2 = ks * 16 + ((r >> 1) & 1) * 8 + (lane & 3) * 2;
            float v0 = invv(n, k2);
            float v1 = invv(n, k2 + 1);
            uint32_t h, l;
            split2(v0, v1, h, l);
            g_WiPHi[strip][ks][lane][r] = h;
            g_WiPLo[strip][ks][lane][r] = l;
        }
    }
}

// ---------------- kernel 2: forward DFT (warp-mma, bf16 multi-pass, split-K) --------
// grid (NSPLIT, 32 bh-pairs, 3 tensors), 256 threads = 8 warps.
// t<2 (Q,K): 3-way split, 6 passes (hh,hm,mh,mm,hl,lh) -> residual ~2^-27.
// t==2 (V):  2-level (h,m), 3 passes -> residual ~2^-18 (linear path, sufficient).
__global__ __launch_bounds__(256) void fwd_mma(const float* __restrict__ q,
                                               const float* __restrict__ k_,
                                               const float* __restrict__ v_) {
    extern __shared__ uint32_t dynsm[];
    uint32_t (*BsH)[64][40] = (uint32_t(*)[64][40])(dynsm);            // 20480 B
    uint32_t (*BsM)[64][40] = (uint32_t(*)[64][40])(dynsm + 5120);     // 20480 B
    uint32_t (*BsL)[64][40] = (uint32_t(*)[64][40])(dynsm + 10240);    // 20480 B
    const int split = blockIdx.x, bp = blockIdx.y, t = blockIdx.z;
    const float* base = (t == 0) ? q : ((t == 1) ? k_ : v_);
    const float* xb0 = base + (size_t)(bp * 2) * LL * DD;
    const float* xb1 = xb0 + (size_t)LL * DD;
    const int tid = threadIdx.x, warp = tid >> 5, lane = tid & 31;
    const int g = lane >> 2, tq = lane & 3;
    const int p = tid & 31, oct = tid >> 5;
    const int w = ((p >> 3) << 3) + ((p & 3) << 1) + ((p >> 2) & 1);
    const bool prec = (t < 2);

    float acc[2][8][4];
#pragma unroll
    for (int b2 = 0; b2 < 2; b2++)
#pragma unroll
        for (int j = 0; j < 8; j++)
#pragma unroll
            for (int i = 0; i < 4; i++) acc[b2][j][i] = 0.0f;

    for (int ch = 0; ch < 8; ch++) {
        const int k0 = split * 512 + ch * 64;
#pragma unroll
        for (int b2 = 0; b2 < 2; b2++) {
            const float* xb = b2 ? xb1 : xb0;
            const float* r0 = xb + (size_t)(k0 + 2 * p) * DD + oct * 8;
            float4 A0 = *(const float4*)(r0);
            float4 A1 = *(const float4*)(r0 + 4);
            float4 B0 = *(const float4*)(r0 + DD);
            float4 B1 = *(const float4*)(r0 + DD + 4);
            float ar[8] = {A0.x, A0.y, A0.z, A0.w, A1.x, A1.y, A1.z, A1.w};
            float br[8] = {B0.x, B0.y, B0.z, B0.w, B1.x, B1.y, B1.z, B1.w};
#pragma unroll
            for (int i = 0; i < 8; i++) {
                uint32_t h, m, l;
                split3(ar[i], br[i], h, m, l);
                BsH[b2][oct * 8 + i][w] = h;
                BsM[b2][oct * 8 + i][w] = m;
                BsL[b2][oct * 8 + i][w] = l;
            }
        }
        __syncthreads();
        const int ksg = split * 32 + ch * 4;
#pragma unroll
        for (int ks4 = 0; ks4 < 4; ks4++) {
            uint4 aH = *(const uint4*)&g_WfPHi[t][warp][ksg + ks4][lane][0];
            uint4 aM = *(const uint4*)&g_WfPMd[t][warp][ksg + ks4][lane][0];
#pragma unroll
            for (int b2 = 0; b2 < 2; b2++)
#pragma unroll
                for (int j = 0; j < 8; j++) {
                    uint2 bH = *(const uint2*)&BsH[b2][j * 8 + g][ks4 * 8 + 2 * tq];
                    uint2 bM = *(const uint2*)&BsM[b2][j * 8 + g][ks4 * 8 + 2 * tq];
                    mma16816(acc[b2][j], aH, bH);
                    mma16816(acc[b2][j], aH, bM);
                    mma16816(acc[b2][j], aM, bH);
                }
            if (prec) {
                uint4 aL = *(const uint4*)&g_WfPLo[t][warp][ksg + ks4][lane][0];
#pragma unroll
                for (int b2 = 0; b2 < 2; b2++)
#pragma unroll
                    for (int j = 0; j < 8; j++) {
                        uint2 bH = *(const uint2*)&BsH[b2][j * 8 + g][ks4 * 8 + 2 * tq];
                        uint2 bM = *(const uint2*)&BsM[b2][j * 8 + g][ks4 * 8 + 2 * tq];
                        uint2 bL = *(const uint2*)&BsL[b2][j * 8 + g][ks4 * 8 + 2 * tq];
                        mma16816(acc[b2][j], aM, bM);
                        mma16816(acc[b2][j], aH, bL);
                        mma16816(acc[b2][j], aL, bH);
                    }
            }
        }
        __syncthreads();
    }
    const int m0 = warp * 16;
#pragma unroll
    for (int b2 = 0; b2 < 2; b2++)
#pragma unroll
        for (int j = 0; j < 8; j++) {
            float* dst = &g_F[t][split][bp * 2 + b2][m0 + g][j * 8 + 2 * tq];
            *(float2*)dst = make_float2(acc[b2][j][0], acc[b2][j][1]);
            *(float2*)(dst + 8 * DD) = make_float2(acc[b2][j][2], acc[b2][j][3]);
        }
}

// ---------------- kernel 3: complex attention over modes + complex tanh ----------------
#define SP 65
__global__ __launch_bounds__(256) void attn_kernel() {
    extern __shared__ float sm[];
    float* Qs = sm;                 // [128][65]
    float* Ks = Qs + MM * SP;
    float* Vs = Ks + MM * SP;
    float* SR = Vs + MM * SP;       // [64][65]
    float* SI = SR + MODES * SP;

    const int bh  = blockIdx.x;
    const int tid = threadIdx.x;

    for (int e = tid; e < MM * DD; e += 256) {
        const int r = e >> 6, d = e & 63;
        float aq = 0.f, ak = 0.f, av = 0.f;
#pragma unroll
        for (int s = 0; s < NSPLIT; s++) {
            aq += g_F[0][s][bh][r][d];
            ak += g_F[1][s][bh][r][d];
            av += g_F[2][s][bh][r][d];
        }
        Qs[r * SP + d] = aq;
        Ks[r * SP + d] = ak;
        Vs[r * SP + d] = av;
    }
    __syncthreads();

    const int tm = tid >> 4;
    const int tn = tid & 15;

    {
        float re[4][4], im[4][4];
#pragma unroll
        for (int i = 0; i < 4; i++)
#pragma unroll
            for (int j = 0; j < 4; j++) { re[i][j] = 0.f; im[i][j] = 0.f; }

        for (int d = 0; d < DD; d++) {
            float qr[4], qi[4], kr[4], ki[4];
#pragma unroll
            for (int i = 0; i < 4; i++) {
                qr[i] = Qs[(tm * 4 + i) * SP + d];
                qi[i] = Qs[(MODES + tm * 4 + i) * SP + d];
            }
#pragma unroll
            for (int j = 0; j < 4; j++) {
                kr[j] = Ks[(tn * 4 + j) * SP + d];
                ki[j] = Ks[(MODES + tn * 4 + j) * SP + d];
            }
#pragma unroll
            for (int i = 0; i < 4; i++)
#pragma unroll
                for (int j = 0; j < 4; j++) {
                    re[i][j] = fmaf(qr[i], kr[j], re[i][j]);
                    re[i][j] = fmaf(-qi[i], ki[j], re[i][j]);
                    im[i][j] = fmaf(qr[i], ki[j], im[i][j]);
                    im[i][j] = fmaf(qi[i], kr[j], im[i][j]);
                }
        }
#pragma unroll
        for (int i = 0; i < 4; i++)
#pragma unroll
            for (int j = 0; j < 4; j++) {
                const float x  = re[i][j] * SCALE;
                const float y  = im[i][j] * SCALE;
                const float x2 = 2.0f * x;
                float tr, ti;
                if (fabsf(x2) > 80.0f) {
                    tr = (x > 0.0f) ? 1.0f : -1.0f;
                    ti = 0.0f;
                } else {
                    const float y2 = 2.0f * y;
                    const float dn = coshf(x2) + cosf(y2);
                    tr = sinhf(x2) / dn;
                    ti = sinf(y2) / dn;
                }
                SR[(tm * 4 + i) * SP + tn * 4 + j] = tr;
                SI[(tm * 4 + i) * SP + tn * 4 + j] = ti;
            }
    }
    __syncthreads();

    {
        float vr[4][4], vi[4][4];
#pragma unroll
        for (int i = 0; i < 4; i++)
#pragma unroll
            for (int j = 0; j < 4; j++) { vr[i][j] = 0.f; vi[i][j] = 0.f; }

        for (int n = 0; n < MODES; n++) {
            float sr[4], si[4], br[4], bi[4];
#pragma unroll
            for (int i = 0; i < 4; i++) {
                sr[i] = SR[(tm * 4 + i) * SP + n];
                si[i] = SI[(tm * 4 + i) * SP + n];
            }
#pragma unroll
            for (int j = 0; j < 4; j++) {
                br[j] = Vs[n * SP + tn * 4 + j];
                bi[j] = Vs[(MODES + n) * SP + tn * 4 + j];
            }
#pragma unroll
            for (int i = 0; i < 4; i++)
#pragma unroll
                for (int j = 0; j < 4; j++) {
                    vr[i][j] = fmaf(sr[i], br[j], vr[i][j]);
                    vr[i][j] = fmaf(-si[i], bi[j], vr[i][j]);
                    vi[i][j] = fmaf(sr[i], bi[j], vi[i][j]);
                    vi[i][j] = fmaf(si[i], br[j], vi[i][j]);
                }
        }
#pragma unroll
        for (int i = 0; i < 4; i++)
#pragma unroll
            for (int j = 0; j < 4; j++) {
                g_V2[bh][tm * 4 + i][tn * 4 + j]         = vr[i][j];
                g_V2[bh][MODES + tm * 4 + i][tn * 4 + j] = vi[i][j];
            }
    }
}

// ---------------- kernel 4: inverse transform (warp-mma, bf16 3-pass) ----------------
__global__ __launch_bounds__(256) void inv_mma(float* __restrict__ out) {
    __shared__ uint32_t BsH[64][72];
    __shared__ uint32_t BsL[64][72];
    const int nt = blockIdx.x, bh = blockIdx.y;
    const int tid = threadIdx.x, warp = tid >> 5, lane = tid & 31;
    const int g = lane >> 2, tq = lane & 3;

    {
        const int pr = tid & 63, quad = tid >> 6;
        const int w = ((pr >> 3) << 3) + ((pr & 3) << 1) + ((pr >> 2) & 1);
        const float* r0 = &g_V2[bh][2 * pr][quad * 16];
#pragma unroll
        for (int c4 = 0; c4 < 4; c4++) {
            float4 a4 = *(const float4*)(r0 + c4 * 4);
            float4 b4 = *(const float4*)(r0 + DD + c4 * 4);
            float ar[4] = {a4.x, a4.y, a4.z, a4.w};
            float br[4] = {b4.x, b4.y, b4.z, b4.w};
#pragma unroll
            for (int i = 0; i < 4; i++) {
                int d = quad * 16 + c4 * 4 + i;
                uint32_t h, l;
                split2(ar[i], br[i], h, l);
                BsH[d][w] = h;
                BsL[d][w] = l;
            }
        }
    }
    __syncthreads();

    float acc[8][4];
#pragma unroll
    for (int j = 0; j < 8; j++)
#pragma unroll
        for (int i = 0; i < 4; i++) acc[j][i] = 0.0f;

#pragma unroll
    for (int ks = 0; ks < 8; ks++) {
        uint4 aH = *(const uint4*)&g_WiPHi[nt * 8 + warp][ks][lane][0];
        uint4 aL = *(const uint4*)&g_WiPLo[nt * 8 + warp][ks][lane][0];
#pragma unroll
        for (int j = 0; j < 8; j++) {
            uint2 bH = *(const uint2*)&BsH[j * 8 + g][ks * 8 + 2 * tq];
            uint2 bL = *(const uint2*)&BsL[j * 8 + g][ks * 8 + 2 * tq];
            mma16816(acc[j], aH, bH);
            mma16816(acc[j], aH, bL);
            mma16816(acc[j], aL, bH);
        }
    }

    const int m0 = warp * 16;
    float* ob = out + ((size_t)bh * LL + (size_t)nt * 128) * DD;
#pragma unroll
    for (int j = 0; j < 8; j++) {
        float* dst = &ob[(m0 + g) * DD + j * 8 + 2 * tq];
        *(float2*)dst = make_float2(acc[j][0], acc[j][1]);
        *(float2*)(dst + 8 * DD) = make_float2(acc[j][2], acc[j][3]);
    }
}

// ---------------- entry point ----------------
extern "C" void kernel_launch(void* const* d_in, const int* in_sizes, int n_in,
                              void* d_out, int out_size) {
    const float* q  = (const float*)d_in[0];
    const float* k  = (const float*)d_in[1];
    const float* v  = (const float*)d_in[2];
    const int* iq   = (const int*)d_in[3];
    const int* ik   = (const int*)d_in[4];
    const int* iv   = (const int*)d_in[5];
    float* out      = (float*)d_out;

    tab_kernel<<<16, 256>>>();
    build_packed<<<1024, 256>>>(iq, ik, iv);

    const int fwd_smem = 3 * 20480;   // 61440 B
    cudaFuncSetAttribute(fwd_mma, cudaFuncAttributeMaxDynamicSharedMemorySize, fwd_smem);
    fwd_mma<<<dim3(NSPLIT, 32, 3), 256, fwd_smem>>>(q, k, v);

    const int attn_smem = (3 * MM + 2 * MODES) * SP * (int)sizeof(float);
    cudaFuncSetAttribute(attn_kernel, cudaFuncAttributeMaxDynamicSharedMemorySize, attn_smem);
    attn_kernel<<<BH, 256, attn_smem>>>();

    inv_mma<<<dim3(32, 64), 256>>>(out);
}

// round 5
// speedup vs baseline: 1.6427x; 1.4886x over previous
#include <cuda_runtime.h>
#include <cuda_fp16.h>
#include <math.h>
#include <cstdint>

#define LL    4096
#define DD    64
#define MODES 64
#define BH    64
#define MM    128
#define NSPLIT 4
#define SCALE 0.125f

// ---------------- globals (no allocation) ----------------
__device__ float2   g_tab[LL];                      // cos/sin(2*pi*r/4096)
__device__ int      g_perm[3][64];                  // parity-sorted mode order per tensor
__device__ int      g_sclass[3][4];                 // strip class: 0=even(Bp) 1=odd(Bm) 2=mixed
__device__ int      g_vmap[64];                     // sigma_v^-1 o sigma_k
__device__ uint32_t g_WfPHi[3][8][2][128][32][4];   // fwd basis frags (K=2048), variant 0/1
__device__ uint32_t g_WfPLo[3][8][2][128][32][4];
__device__ uint32_t g_WiPHi[256][8][32][4];         // inv basis frags (x1024 scaled)
__device__ uint32_t g_WiPLo[256][8][32][4];
__device__ float    g_F[3][NSPLIT][BH][MM][DD];     // split-K partials (storage mode order)
__device__ float    g_Ffin[3][BH][MM][DD];          // reduced spectra
__device__ float    g_V2[BH][MM][DD];               // post-attention values

// ---------------- helpers ----------------
__device__ __forceinline__ uint32_t packh(__half a, __half b) {
    return (uint32_t)__half_as_ushort(a) | ((uint32_t)__half_as_ushort(b) << 16);
}
__device__ __forceinline__ void split2h(float a, float b, uint32_t& h, uint32_t& l) {
    __half ha = __float2half_rn(a), hb = __float2half_rn(b);
    __half la = __float2half_rn(a - __half2float(ha));
    __half lb = __float2half_rn(b - __half2float(hb));
    h = packh(ha, hb);
    l = packh(la, lb);
}
__device__ __forceinline__ void mma16816h(float* c, const uint4& a, const uint2& b) {
    asm volatile(
        "mma.sync.aligned.m16n8k16.row.col.f32.f16.f16.f32 "
        "{%0,%1,%2,%3}, {%4,%5,%6,%7}, {%8,%9}, {%0,%1,%2,%3};"
        : "+f"(c[0]), "+f"(c[1]), "+f"(c[2]), "+f"(c[3])
        : "r"(a.x), "r"(a.y), "r"(a.z), "r"(a.w), "r"(b.x), "r"(b.y));
}

// ---------------- kernel 0: phase table + permutations ----------------
__global__ __launch_bounds__(256) void tab_kernel(const int* __restrict__ iq,
                                                  const int* __restrict__ ik,
                                                  const int* __restrict__ iv) {
    int r = blockIdx.x * blockDim.x + threadIdx.x;
    if (r < LL) {
        float s, c;
        sincospif((float)r * (1.0f / 2048.0f), &s, &c);
        g_tab[r] = make_float2(c, s);
    }
    if (blockIdx.x == 0 && threadIdx.x == 0) {
        for (int t = 0; t < 3; t++) {
            const int* ix = (t == 0) ? iq : ((t == 1) ? ik : iv);
            int pm[64], ne = 0;
            for (int i = 0; i < 64; i++) if ((ix[i] & 1) == 0) pm[ne++] = i;
            int no = ne;
            for (int i = 0; i < 64; i++) if (ix[i] & 1) pm[no++] = i;
            for (int i = 0; i < 64; i++) g_perm[t][i] = pm[i];
            for (int s4 = 0; s4 < 4; s4++) {
                int st0 = s4 * 16, st1 = st0 + 15;
                g_sclass[t][s4] = (st1 < ne) ? 0 : ((st0 >= ne) ? 1 : 2);
            }
        }
        int ipv[64];
        for (int i = 0; i < 64; i++) ipv[g_perm[2][i]] = i;
        for (int s4 = 0; s4 < 64; s4++) g_vmap[s4] = ipv[g_perm[1][s4]];
    }
}

// ---------------- kernel 1: build fragment-packed bases ----------------
#define FWDN (3 * 8 * 2 * 128 * 32 * 4)   // 786432
#define INVN (256 * 8 * 32 * 4)           // 262144

__device__ __forceinline__ float invv_p(int n, int k2) {
    int gq = g_perm[0][k2 & 63];    // frequency bin (permuted q-mode order), x1024 scale
    if (gq == 0) return (k2 < 64) ? (1024.0f / (float)LL) : 0.0f;
    int r = (gq * n) & (LL - 1);
    return (k2 < 64) ? (2048.0f / (float)LL) * g_tab[r].x
                     : -(2048.0f / (float)LL) * g_tab[r].y;
}

__global__ __launch_bounds__(256) void build_packed(const int* __restrict__ iq,
                                                    const int* __restrict__ ik,
                                                    const int* __restrict__ iv) {
    for (int gid = blockIdx.x * blockDim.x + threadIdx.x; gid < FWDN + INVN;
         gid += gridDim.x * blockDim.x) {
        if (gid < FWDN) {
            int r    = gid & 3;
            int lane = (gid >> 2) & 31;
            int ks   = (gid >> 7) & 127;
            int vv   = (gid >> 14) & 1;
            int s    = (gid >> 15) & 7;
            int t    = gid >> 18;
            int m_local = s * 16 + (r & 1) * 8 + (lane >> 2);
            int mode_st = m_local & 63;
            const int* ix = (t == 0) ? iq : ((t == 1) ? ik : iv);
            int f = ix[g_perm[t][mode_st]];
            float v0 = 0.0f, v1 = 0.0f;
            if ((f & 1) == vv) {
                int k = ks * 16 + ((r >> 1) & 1) * 8 + (lane & 3) * 2;
                int r1 = (f * k) & (LL - 1);
                int r2 = (r1 + f) & (LL - 1);
                float2 c1 = g_tab[r1], c2 = g_tab[r2];
                v0 = (m_local < MODES) ? c1.x : -c1.y;
                v1 = (m_local < MODES) ? c2.x : -c2.y;
            }
            uint32_t h, l;
            split2h(v0, v1, h, l);
            g_WfPHi[t][s][vv][ks][lane][r] = h;
            g_WfPLo[t][s][vv][ks][lane][r] = l;
        } else {
            int g2    = gid - FWDN;
            int r     = g2 & 3;
            int lane  = (g2 >> 2) & 31;
            int ks    = (g2 >> 7) & 7;
            int strip = g2 >> 10;
            int n  = strip * 16 + (r & 1) * 8 + (lane >> 2);
            int k2 = ks * 16 + ((r >> 1) & 1) * 8 + (lane & 3) * 2;
            float v0 = invv_p(n, k2);
            float v1 = invv_p(n, k2 + 1);
            uint32_t h, l;
            split2h(v0, v1, h, l);
            g_WiPHi[strip][ks][lane][r] = h;
            g_WiPLo[strip][ks][lane][r] = l;
        }
    }
}

// ---------------- kernel 2: forward DFT (fold-by-2, fp16 3-pass, split-K) ----------
// grid (NSPLIT, 64, 3), 256 threads = 8 warps; warp handles rotated strip s.
__global__ __launch_bounds__(256) void fwd_mma(const float* __restrict__ q,
                                               const float* __restrict__ k_,
                                               const float* __restrict__ v_) {
    __shared__ uint32_t BpH[64][40], BpL[64][40], BmH[64][40], BmL[64][40];
    const int split = blockIdx.x, bh = blockIdx.y, t = blockIdx.z;
    const float* xb = ((t == 0) ? q : ((t == 1) ? k_ : v_)) + (size_t)bh * LL * DD;
    const int tid = threadIdx.x, warp = tid >> 5, lane = tid & 31;
    const int g = lane >> 2, tq = lane & 3;
    const int s = (warp + bh + split) & 7;        // rotated strip -> SMSP load balance
    const int cls = g_sclass[t][s & 3];
    const int p = tid & 31, oct = tid >> 5;
    const int w = ((p >> 3) << 3) + ((p & 3) << 1) + ((p >> 2) & 1);

    float acc[8][4];
#pragma unroll
    for (int j = 0; j < 8; j++)
#pragma unroll
        for (int i = 0; i < 4; i++) acc[j][i] = 0.0f;

    for (int ch = 0; ch < 8; ch++) {
        const int k0 = split * 512 + ch * 64;
        {
            const float* r00 = xb + (size_t)(k0 + 2 * p) * DD + oct * 8;
            const float* r10 = r00 + (size_t)2048 * DD;
            float4 A0 = *(const float4*)(r00);
            float4 A1 = *(const float4*)(r00 + 4);
            float4 B0 = *(const float4*)(r00 + DD);
            float4 B1 = *(const float4*)(r00 + DD + 4);
            float4 C0 = *(const float4*)(r10);
            float4 C1 = *(const float4*)(r10 + 4);
            float4 D0 = *(const float4*)(r10 + DD);
            float4 D1 = *(const float4*)(r10 + DD + 4);
            float al[8] = {A0.x, A0.y, A0.z, A0.w, A1.x, A1.y, A1.z, A1.w};
            float bl[8] = {B0.x, B0.y, B0.z, B0.w, B1.x, B1.y, B1.z, B1.w};
            float ch_[8] = {C0.x, C0.y, C0.z, C0.w, C1.x, C1.y, C1.z, C1.w};
            float dh[8] = {D0.x, D0.y, D0.z, D0.w, D1.x, D1.y, D1.z, D1.w};
#pragma unroll
            for (int i = 0; i < 8; i++) {
                uint32_t h, l;
                split2h(al[i] + ch_[i], bl[i] + dh[i], h, l);
                BpH[oct * 8 + i][w] = h;
                BpL[oct * 8 + i][w] = l;
                split2h(al[i] - ch_[i], bl[i] - dh[i], h, l);
                BmH[oct * 8 + i][w] = h;
                BmL[oct * 8 + i][w] = l;
            }
        }
        __syncthreads();
        const int ksg = split * 32 + ch * 4;
#pragma unroll
        for (int ks4 = 0; ks4 < 4; ks4++) {
            if (cls != 1) {
                uint4 aH = *(const uint4*)&g_WfPHi[t][s][0][ksg + ks4][lane][0];
                uint4 aL = *(const uint4*)&g_WfPLo[t][s][0][ksg + ks4][lane][0];
#pragma unroll
                for (int j = 0; j < 8; j++) {
                    uint2 bH = *(const uint2*)&BpH[j * 8 + g][ks4 * 8 + 2 * tq];
                    uint2 bL = *(const uint2*)&BpL[j * 8 + g][ks4 * 8 + 2 * tq];
                    mma16816h(acc[j], aH, bH);
                    mma16816h(acc[j], aH, bL);
                    mma16816h(acc[j], aL, bH);
                }
            }
            if (cls != 0) {
                uint4 aH = *(const uint4*)&g_WfPHi[t][s][1][ksg + ks4][lane][0];
                uint4 aL = *(const uint4*)&g_WfPLo[t][s][1][ksg + ks4][lane][0];
#pragma unroll
                for (int j = 0; j < 8; j++) {
                    uint2 bH = *(const uint2*)&BmH[j * 8 + g][ks4 * 8 + 2 * tq];
                    uint2 bL = *(const uint2*)&BmL[j * 8 + g][ks4 * 8 + 2 * tq];
                    mma16816h(acc[j], aH, bH);
                    mma16816h(acc[j], aH, bL);
                    mma16816h(acc[j], aL, bH);
                }
            }
        }
        __syncthreads();
    }
    const int m0 = s * 16;
#pragma unroll
    for (int j = 0; j < 8; j++) {
        float* dst = &g_F[t][split][bh][m0 + g][j * 8 + 2 * tq];
        *(float2*)dst = make_float2(acc[j][0], acc[j][1]);
        *(float2*)(dst + 8 * DD) = make_float2(acc[j][2], acc[j][3]);
    }
}

// ---------------- kernel 3: reduce split-K partials ----------------
__global__ __launch_bounds__(256) void reduce_kernel() {
    const int TOT = 3 * BH * MM * DD / 4;   // 393216 float4
    int i = blockIdx.x * blockDim.x + threadIdx.x;
    if (i >= TOT) return;
    const int PER_T = BH * MM * DD / 4;     // 131072
    int t = i / PER_T;
    int r = i - t * PER_T;
    const float4* base = (const float4*)&g_F[t][0][0][0][0];
    float4 a = base[r];
#pragma unroll
    for (int s = 1; s < NSPLIT; s++) {
        float4 b = base[s * PER_T + r];
        a.x += b.x; a.y += b.y; a.z += b.z; a.w += b.w;
    }
    ((float4*)g_Ffin)[i] = a;
}

// ---------------- kernel 4: complex attention over modes + complex tanh ----------------
#define SP 65
__global__ __launch_bounds__(256) void attn_kernel() {
    extern __shared__ float sm[];
    float* Qs = sm;                 // [128][65]
    float* Ks = Qs + MM * SP;
    float* Vs = Ks + MM * SP;
    float* SR = Vs + MM * SP;       // [64][65]
    float* SI = SR + MODES * SP;

    const int bh  = blockIdx.x;
    const int tid = threadIdx.x;

    for (int e = tid; e < MM * DD; e += 256) {
        const int r = e >> 6, d = e & 63;
        Qs[r * SP + d] = g_Ffin[0][bh][r][d];
        Ks[r * SP + d] = g_Ffin[1][bh][r][d];
        // V rows remapped so position pairs with K storage order
        int vrow = ((r >= 64) ? 64 : 0) + __ldg(&g_vmap[r & 63]);
        Vs[r * SP + d] = g_Ffin[2][bh][vrow][d];
    }
    __syncthreads();

    const int tm = tid >> 4;
    const int tn = tid & 15;

    {
        float re[4][4], im[4][4];
#pragma unroll
        for (int i = 0; i < 4; i++)
#pragma unroll
            for (int j = 0; j < 4; j++) { re[i][j] = 0.f; im[i][j] = 0.f; }

        for (int d = 0; d < DD; d++) {
            float qr[4], qi[4], kr[4], ki[4];
#pragma unroll
            for (int i = 0; i < 4; i++) {
                qr[i] = Qs[(tm * 4 + i) * SP + d];
                qi[i] = Qs[(MODES + tm * 4 + i) * SP + d];
            }
#pragma unroll
            for (int j = 0; j < 4; j++) {
                kr[j] = Ks[(tn * 4 + j) * SP + d];
                ki[j] = Ks[(MODES + tn * 4 + j) * SP + d];
            }
#pragma unroll
            for (int i = 0; i < 4; i++)
#pragma unroll
                for (int j = 0; j < 4; j++) {
                    re[i][j] = fmaf(qr[i], kr[j], re[i][j]);
                    re[i][j] = fmaf(-qi[i], ki[j], re[i][j]);
                    im[i][j] = fmaf(qr[i], ki[j], im[i][j]);
                    im[i][j] = fmaf(qi[i], kr[j], im[i][j]);
                }
        }
#pragma unroll
        for (int i = 0; i < 4; i++)
#pragma unroll
            for (int j = 0; j < 4; j++) {
                const float x  = re[i][j] * SCALE;
                const float y  = im[i][j] * SCALE;
                const float x2 = 2.0f * x;
                float tr, ti;
                if (fabsf(x2) > 80.0f) {
                    tr = (x > 0.0f) ? 1.0f : -1.0f;
                    ti = 0.0f;
                } else {
                    const float y2 = 2.0f * y;
                    const float dn = coshf(x2) + cosf(y2);
                    tr = sinhf(x2) / dn;
                    ti = sinf(y2) / dn;
                }
                SR[(tm * 4 + i) * SP + tn * 4 + j] = tr;
                SI[(tm * 4 + i) * SP + tn * 4 + j] = ti;
            }
    }
    __syncthreads();

    {
        float vr[4][4], vi[4][4];
#pragma unroll
        for (int i = 0; i < 4; i++)
#pragma unroll
            for (int j = 0; j < 4; j++) { vr[i][j] = 0.f; vi[i][j] = 0.f; }

        for (int n = 0; n < MODES; n++) {
            float sr[4], si[4], br[4], bi[4];
#pragma unroll
            for (int i = 0; i < 4; i++) {
                sr[i] = SR[(tm * 4 + i) * SP + n];
                si[i] = SI[(tm * 4 + i) * SP + n];
            }
#pragma unroll
            for (int j = 0; j < 4; j++) {
                br[j] = Vs[n * SP + tn * 4 + j];
                bi[j] = Vs[(MODES + n) * SP + tn * 4 + j];
            }
#pragma unroll
            for (int i = 0; i < 4; i++)
#pragma unroll
                for (int j = 0; j < 4; j++) {
                    vr[i][j] = fmaf(sr[i], br[j], vr[i][j]);
                    vr[i][j] = fmaf(-si[i], bi[j], vr[i][j]);
                    vi[i][j] = fmaf(sr[i], bi[j], vi[i][j]);
                    vi[i][j] = fmaf(si[i], br[j], vi[i][j]);
                }
        }
#pragma unroll
        for (int i = 0; i < 4; i++)
#pragma unroll
            for (int j = 0; j < 4; j++) {
                g_V2[bh][tm * 4 + i][tn * 4 + j]         = vr[i][j];
                g_V2[bh][MODES + tm * 4 + i][tn * 4 + j] = vi[i][j];
            }
    }
}

// ---------------- kernel 5: inverse transform (fp16 3-pass) ----------------
#define ISC (1.0f / 1024.0f)
__global__ __launch_bounds__(256) void inv_mma(float* __restrict__ out) {
    __shared__ uint32_t BsH[64][72];
    __shared__ uint32_t BsL[64][72];
    const int nt = blockIdx.x, bh = blockIdx.y;
    const int tid = threadIdx.x, warp = tid >> 5, lane = tid & 31;
    const int g = lane >> 2, tq = lane & 3;

    {
        const int pr = tid & 63, quad = tid >> 6;
        const int w = ((pr >> 3) << 3) + ((pr & 3) << 1) + ((pr >> 2) & 1);
        const float* r0 = &g_V2[bh][2 * pr][quad * 16];
#pragma unroll
        for (int c4 = 0; c4 < 4; c4++) {
            float4 a4 = *(const float4*)(r0 + c4 * 4);
            float4 b4 = *(const float4*)(r0 + DD + c4 * 4);
            float ar[4] = {a4.x, a4.y, a4.z, a4.w};
            float br[4] = {b4.x, b4.y, b4.z, b4.w};
#pragma unroll
            for (int i = 0; i < 4; i++) {
                int d = quad * 16 + c4 * 4 + i;
                uint32_t h, l;
                split2h(ar[i] * ISC, br[i] * ISC, h, l);
                BsH[d][w] = h;
                BsL[d][w] = l;
            }
        }
    }
    __syncthreads();

    float acc[8][4];
#pragma unroll
    for (int j = 0; j < 8; j++)
#pragma unroll
        for (int i = 0; i < 4; i++) acc[j][i] = 0.0f;

#pragma unroll
    for (int ks = 0; ks < 8; ks++) {
        uint4 aH = *(const uint4*)&g_WiPHi[nt * 8 + warp][ks][lane][0];
        uint4 aL = *(const uint4*)&g_WiPLo[nt * 8 + warp][ks][lane][0];
#pragma unroll
        for (int j = 0; j < 8; j++) {
            uint2 bH = *(const uint2*)&BsH[j * 8 + g][ks * 8 + 2 * tq];
            uint2 bL = *(const uint2*)&BsL[j * 8 + g][ks * 8 + 2 * tq];
            mma16816h(acc[j], aH, bH);
            mma16816h(acc[j], aH, bL);
            mma16816h(acc[j], aL, bH);
        }
    }

    const int m0 = warp * 16;
    float* ob = out + ((size_t)bh * LL + (size_t)nt * 128) * DD;
#pragma unroll
    for (int j = 0; j < 8; j++) {
        float* dst = &ob[(m0 + g) * DD + j * 8 + 2 * tq];
        *(float2*)dst = make_float2(acc[j][0], acc[j][1]);
        *(float2*)(dst + 8 * DD) = make_float2(acc[j][2], acc[j][3]);
    }
}

// ---------------- entry point ----------------
extern "C" void kernel_launch(void* const* d_in, const int* in_sizes, int n_in,
                              void* d_out, int out_size) {
    const float* q  = (const float*)d_in[0];
    const float* k  = (const float*)d_in[1];
    const float* v  = (const float*)d_in[2];
    const int* iq   = (const int*)d_in[3];
    const int* ik   = (const int*)d_in[4];
    const int* iv   = (const int*)d_in[5];
    float* out      = (float*)d_out;

    tab_kernel<<<16, 256>>>(iq, ik, iv);
    build_packed<<<1024, 256>>>(iq, ik, iv);

    fwd_mma<<<dim3(NSPLIT, BH, 3), 256>>>(q, k, v);

    reduce_kernel<<<1536, 256>>>();

    const int attn_smem = (3 * MM + 2 * MODES) * SP * (int)sizeof(float);
    cudaFuncSetAttribute(attn_kernel, cudaFuncAttributeMaxDynamicSharedMemorySize, attn_smem);
    attn_kernel<<<BH, 256, attn_smem>>>();

    inv_mma<<<dim3(32, 64), 256>>>(out);
}